// round 3
// baseline (speedup 1.0000x reference)
#include <cuda_runtime.h>

#define NB     32
#define NT     256
#define NITER  200
#define LROWS  8192

// err = 2^(-2*bits), bits = {2,3,4,5,6,8,10,12}
__constant__ float c_err[8] = {
    6.25e-2f, 1.5625e-2f, 3.90625e-3f, 9.765625e-4f,
    2.44140625e-4f, 1.52587890625e-5f, 9.5367431640625e-7f, 5.9604644775390625e-8f
};

__device__ float g_sum_n;
__device__ float g_inv_sens;
// ring of 2 slots; 32 blocks * 8 cols = 256 published partials per slot
__device__ float g_part[2][256];

__device__ __forceinline__ float ld_cg(const float* p) {
    float v;
    asm volatile("ld.global.cg.f32 %0, [%1];" : "=f"(v) : "l"(p) : "memory");
    return v;
}
__device__ __forceinline__ void st_cg(float* p, float v) {
    asm volatile("st.global.cg.f32 [%0], %1;" :: "l"(p), "f"(v) : "memory");
}
__device__ __forceinline__ float ex2f(float x) {
    float y; asm("ex2.approx.f32 %0, %1;" : "=f"(y) : "f"(x)); return y;
}
__device__ __forceinline__ float lg2f(float x) {
    float y; asm("lg2.approx.f32 %0, %1;" : "=f"(y) : "f"(x)); return y;
}

// ---------------------------------------------------------------------------
// Pre-kernel: input sums + ring init (-0.0 => sign bit 1) for graph replays
// ---------------------------------------------------------------------------
__global__ void da_pre_kernel(const float* __restrict__ n_raw,
                              const float* __restrict__ sens_raw) {
    __shared__ float s1[NT / 32], s2[NT / 32];
    int t = threadIdx.x;
    float sn = 0.f, ss = 0.f;
    for (int i = t; i < LROWS; i += NT) { sn += n_raw[i]; ss += sens_raw[i]; }
#pragma unroll
    for (int o = 16; o; o >>= 1) {
        sn += __shfl_xor_sync(0xffffffffu, sn, o);
        ss += __shfl_xor_sync(0xffffffffu, ss, o);
    }
    if ((t & 31) == 0) { s1[t >> 5] = sn; s2[t >> 5] = ss; }
    __syncthreads();
    if (t == 0) {
        float a = 0.f, b = 0.f;
#pragma unroll
        for (int w = 0; w < NT / 32; w++) { a += s1[w]; b += s2[w]; }
        g_sum_n    = a * 1e5f + 1e3f * (float)LROWS;
        g_inv_sens = 1.0f / (b + 1e-12f);
    }
    float* ring = (float*)g_part;
    const float neg0 = __int_as_float(0x80000000u);
    for (int i = t; i < 2 * 256; i += NT) ring[i] = neg0;
}

// ---------------------------------------------------------------------------
// Main kernel: 32 blocks x 256 threads, one row per thread (8 cols in regs).
// Only warp 0 of each block publishes/polls the 256 global partials.
// ---------------------------------------------------------------------------
__global__ void __launch_bounds__(NT, 1)
da_main_kernel(const float* __restrict__ theta,
               const float* __restrict__ phi,
               const float* __restrict__ sens_raw,
               const float* __restrict__ n_raw,
               float* __restrict__ out) {
    const int tid  = threadIdx.x;
    const int lane = tid & 31;
    const int warp = tid >> 5;
    const int row  = blockIdx.x * NT + tid;
    const unsigned FULL = 0xffffffffu;
    const float L2E = 1.4426950408889634f;

    __shared__ float sred[8][8];   // per-warp column partials
    __shared__ float sg[8];        // broadcast: new g (base-2)
    __shared__ float sT[8];        // broadcast: column sums T
    __shared__ int   sconv;        // broadcast: convergence flag

    // ---- warp-0 per-column scalars (lane c owns column c, c = lane&7)
    const int mycol = lane & 7;
    float lb_c, gcur_c = 0.0f, gm1_c = __int_as_float(0x7f000000u);
    {
        // log_b (base 2) for this lane's column, from full phi
        float q[8];
#pragma unroll
        for (int j = 0; j < 8; j++) q[j] = phi[j] * L2E;
        float m = fmaxf(fmaxf(fmaxf(q[0], q[1]), fmaxf(q[2], q[3])),
                        fmaxf(fmaxf(q[4], q[5]), fmaxf(q[6], q[7])));
        float s = 0.f;
#pragma unroll
        for (int j = 0; j < 8; j++) s += ex2f(q[j] - m);
        lb_c = phi[mycol] * L2E - m - lg2f(s);
    }

    // ---- K in base-2: K2 = (theta - C) * 50 * log2e
    const float inv_sumn = 1.0f / g_sum_n;
    float n  = n_raw[row] * 1e5f + 1e3f;
    float a  = n * inv_sumn;
    float cs = n * sens_raw[row] * g_inv_sens;
    const float SC = 50.0f * L2E;
    float K2[8];
    {
        const float4* t4 = (const float4*)theta;
        float4 ta = t4[row * 2], tb = t4[row * 2 + 1];
        K2[0] = (ta.x - cs * c_err[0]) * SC;
        K2[1] = (ta.y - cs * c_err[1]) * SC;
        K2[2] = (ta.z - cs * c_err[2]) * SC;
        K2[3] = (ta.w - cs * c_err[3]) * SC;
        K2[4] = (tb.x - cs * c_err[4]) * SC;
        K2[5] = (tb.y - cs * c_err[5]) * SC;
        K2[6] = (tb.z - cs * c_err[6]) * SC;
        K2[7] = (tb.w - cs * c_err[7]) * SC;
    }

    float G2[8], Gm1[8], p[8];
#pragma unroll
    for (int j = 0; j < 8; j++) { G2[j] = 0.f; Gm1[j] = __int_as_float(0x7f000000u); }

    for (int it = 0; it < NITER; ++it) {
        const int      slot = it & 1;
        const unsigned esgn = (unsigned)((it >> 1) & 1);

        // ---- row step (in-thread): row softmax, P entries
        float x[8];
#pragma unroll
        for (int j = 0; j < 8; j++) x[j] = K2[j] + G2[j];
        float m2 = fmaxf(fmaxf(fmaxf(x[0], x[1]), fmaxf(x[2], x[3])),
                         fmaxf(fmaxf(x[4], x[5]), fmaxf(x[6], x[7])));
        float S = 0.f;
#pragma unroll
        for (int j = 0; j < 8; j++) { p[j] = ex2f(x[j] - m2); S += p[j]; }
        float ar = __fdividef(a, S);
#pragma unroll
        for (int j = 0; j < 8; j++) p[j] *= ar;   // P_ij = exp(K + f + g_old)

        // ---- butterfly transpose-reduce: lane holds col sum for col (lane&7)
        float z;
        {
            float s0 = __shfl_xor_sync(FULL, p[0], 4);
            float s1 = __shfl_xor_sync(FULL, p[1], 4);
            float s2 = __shfl_xor_sync(FULL, p[2], 4);
            float s3 = __shfl_xor_sync(FULL, p[3], 4);
            float s4 = __shfl_xor_sync(FULL, p[4], 4);
            float s5 = __shfl_xor_sync(FULL, p[5], 4);
            float s6 = __shfl_xor_sync(FULL, p[6], 4);
            float s7 = __shfl_xor_sync(FULL, p[7], 4);
            bool hi4 = (lane & 4) != 0;
            float u0 = hi4 ? (p[4] + s4) : (p[0] + s0);
            float u1 = hi4 ? (p[5] + s5) : (p[1] + s1);
            float u2 = hi4 ? (p[6] + s6) : (p[2] + s2);
            float u3 = hi4 ? (p[7] + s7) : (p[3] + s3);
            float r0 = __shfl_xor_sync(FULL, u0, 2);
            float r1 = __shfl_xor_sync(FULL, u1, 2);
            float r2 = __shfl_xor_sync(FULL, u2, 2);
            float r3 = __shfl_xor_sync(FULL, u3, 2);
            bool hi2 = (lane & 2) != 0;
            float w0 = hi2 ? (u2 + r2) : (u0 + r0);
            float w1 = hi2 ? (u3 + r3) : (u1 + r1);
            float q0 = __shfl_xor_sync(FULL, w0, 1);
            float q1 = __shfl_xor_sync(FULL, w1, 1);
            z = (lane & 1) ? (w1 + q1) : (w0 + q0);
            z += __shfl_xor_sync(FULL, z, 8);
            z += __shfl_xor_sync(FULL, z, 16);
        }
        if (lane < 8) sred[warp][lane] = z;
        __syncthreads();

        // ---- warp 0: block combine, publish, poll, reduce, g update
        if (warp == 0) {
            if (lane < 8) {
                float t = ((sred[0][lane] + sred[1][lane]) + (sred[2][lane] + sred[3][lane]))
                        + ((sred[4][lane] + sred[5][lane]) + (sred[6][lane] + sred[7][lane]));
                float val = t + 1e-35f;
                st_cg(&g_part[slot][(blockIdx.x << 3) + lane], esgn ? -val : val);
            }

            // poll all 256 published partials: lane reads idx = lane + 32k
            float    v[8];
            unsigned mask = 0;
            const float* bp = g_part[slot];
            while (mask != 0xffu) {
#pragma unroll
                for (int k = 0; k < 8; k++) {
                    if (!((mask >> k) & 1u)) {
                        float xv = ld_cg(bp + lane + (k << 5));
                        if ((__float_as_uint(xv) >> 31) == esgn) {
                            v[k] = fabsf(xv);
                            mask |= (1u << k);
                        }
                    }
                }
            }
            // lane's 8 values are all column (lane&7); combine across lanes 8,16
            float cT = ((v[0] + v[1]) + (v[2] + v[3])) + ((v[4] + v[5]) + (v[6] + v[7]));
            cT += __shfl_xor_sync(FULL, cT, 8);
            cT += __shfl_xor_sync(FULL, cT, 16);

            // g update in lanes 0-7 only (8 lg2 per block total)
            float gn = lb_c + gcur_c - lg2f(fmaxf(cT, 1e-37f));
            bool cb  = (__float_as_uint(gn) == __float_as_uint(gm1_c));
            unsigned bal = __ballot_sync(FULL, (lane < 8) ? cb : true);
            if (lane < 8) {
                sg[lane] = gn;
                sT[lane] = cT;
                gm1_c = gcur_c;
                gcur_c = gn;
            }
            if (lane == 0)
                sconv = (bal == FULL && (it & 1) == 1) ? 1 : 0;
        }
        __syncthreads();

        // ---- broadcast new g to all threads
#pragma unroll
        for (int j = 0; j < 8; j++) { Gm1[j] = G2[j]; G2[j] = sg[j]; }
        // period-2 exact fixed point: remaining iterations are exact no-ops
        if (sconv) break;
    }

    // ---- final plan: P = p * exp2(G2 - Gm1); total = sum_j T_j * ed_j
    float tot = 0.f, ed[8];
#pragma unroll
    for (int j = 0; j < 8; j++) { ed[j] = ex2f(G2[j] - Gm1[j]); tot += sT[j] * ed[j]; }
    float inv = 1.0f / (tot + 1e-40f);

    float4 o0, o1;
    o0.x = p[0] * ed[0] * inv;  o0.y = p[1] * ed[1] * inv;
    o0.z = p[2] * ed[2] * inv;  o0.w = p[3] * ed[3] * inv;
    o1.x = p[4] * ed[4] * inv;  o1.y = p[5] * ed[5] * inv;
    o1.z = p[6] * ed[6] * inv;  o1.w = p[7] * ed[7] * inv;
    float4* out4 = (float4*)out;
    out4[row * 2]     = o0;
    out4[row * 2 + 1] = o1;
}

// ---------------------------------------------------------------------------
extern "C" void kernel_launch(void* const* d_in, const int* in_sizes, int n_in,
                              void* d_out, int out_size) {
    const float* theta    = (const float*)d_in[0];
    const float* phi      = (const float*)d_in[1];
    const float* sens_raw = (const float*)d_in[2];
    const float* n_raw    = (const float*)d_in[3];
    float*       out      = (float*)d_out;

    da_pre_kernel<<<1, NT>>>(n_raw, sens_raw);
    da_main_kernel<<<NB, NT>>>(theta, phi, sens_raw, n_raw, out);
}

// round 4
// speedup vs baseline: 1.7497x; 1.7497x over previous
#include <cuda_runtime.h>

#define NCTA   8
#define NT     256
#define NWARP  8                 // warps per CTA
#define GWARPS (NCTA * NWARP)    // 64 publishing warps
#define RPT    4                 // rows per thread: 8*256*4 = 8192
#define NITER  200
#define LROWS  8192

// err = 2^(-2*bits), bits = {2,3,4,5,6,8,10,12}
__constant__ float c_err[8] = {
    6.25e-2f, 1.5625e-2f, 3.90625e-3f, 9.765625e-4f,
    2.44140625e-4f, 1.52587890625e-5f, 9.5367431640625e-7f, 5.9604644775390625e-8f
};

__device__ float g_sum_n;
__device__ float g_inv_sens;

__device__ __forceinline__ float ex2f(float x) {
    float y; asm("ex2.approx.f32 %0, %1;" : "=f"(y) : "f"(x)); return y;
}
__device__ __forceinline__ float lg2f(float x) {
    float y; asm("lg2.approx.f32 %0, %1;" : "=f"(y) : "f"(x)); return y;
}
__device__ __forceinline__ unsigned smem_u32(const void* p) {
    unsigned a;
    asm("{ .reg .u64 t; cvta.to.shared.u64 t, %1; cvt.u32.u64 %0, t; }"
        : "=r"(a) : "l"(p));
    return a;
}
__device__ __forceinline__ unsigned mapa_u32(unsigned laddr, unsigned rank) {
    unsigned r;
    asm("mapa.shared::cluster.u32 %0, %1, %2;" : "=r"(r) : "r"(laddr), "r"(rank));
    return r;
}
__device__ __forceinline__ void st_cluster(unsigned addr, unsigned bits) {
    asm volatile("st.relaxed.cluster.shared::cluster.u32 [%0], %1;"
                 :: "r"(addr), "r"(bits) : "memory");
}
__device__ __forceinline__ unsigned ld_vol_shared(unsigned addr) {
    unsigned v;
    asm volatile("ld.volatile.shared.u32 %0, [%1];" : "=r"(v) : "r"(addr) : "memory");
    return v;
}

// ---------------------------------------------------------------------------
// Pre-kernel: global input sums (graph-replay deterministic)
// ---------------------------------------------------------------------------
__global__ void da_pre_kernel(const float* __restrict__ n_raw,
                              const float* __restrict__ sens_raw) {
    __shared__ float s1[NT / 32], s2[NT / 32];
    int t = threadIdx.x;
    float sn = 0.f, ss = 0.f;
    for (int i = t; i < LROWS; i += NT) { sn += n_raw[i]; ss += sens_raw[i]; }
#pragma unroll
    for (int o = 16; o; o >>= 1) {
        sn += __shfl_xor_sync(0xffffffffu, sn, o);
        ss += __shfl_xor_sync(0xffffffffu, ss, o);
    }
    if ((t & 31) == 0) { s1[t >> 5] = sn; s2[t >> 5] = ss; }
    __syncthreads();
    if (t == 0) {
        float a = 0.f, b = 0.f;
#pragma unroll
        for (int w = 0; w < NT / 32; w++) { a += s1[w]; b += s2[w]; }
        g_sum_n    = a * 1e5f + 1e3f * (float)LROWS;
        g_inv_sens = 1.0f / (b + 1e-12f);
    }
}

// ---------------------------------------------------------------------------
// Main kernel: one cluster of 8 CTAs x 256 threads, 4 rows/thread (8 cols ea).
// All-to-all column-sum exchange over DSMEM; warps fully independent (no bars).
// ---------------------------------------------------------------------------
__global__ void __launch_bounds__(NT, 1) __cluster_dims__(NCTA, 1, 1)
da_main_kernel(const float* __restrict__ theta,
               const float* __restrict__ phi,
               const float* __restrict__ sens_raw,
               const float* __restrict__ n_raw,
               float* __restrict__ out) {
    // poll buffer: 2 slots x (64 warps x 8 cols); slot stride = 2048 bytes
    __shared__ unsigned sbuf[2][GWARPS * 8];

    const int tid  = threadIdx.x;
    const int lane = tid & 31;
    const int warp = tid >> 5;
    const unsigned FULL = 0xffffffffu;
    const float L2E = 1.4426950408889634f;

    unsigned rank;
    asm("mov.u32 %0, %%cluster_ctarank;" : "=r"(rank));
    const int gw   = (int)rank * NWARP + warp;          // global warp id 0..63
    const int base = ((int)rank * NT + tid) * RPT;      // first row of this thread

    // ---- init poll buffers to phase-sign 1 (never matches it=0/1 expect of 0)
    const unsigned sbase = smem_u32(&sbuf[0][0]);
#pragma unroll
    for (int i = tid; i < 2 * GWARPS * 8; i += NT) ((unsigned*)sbuf)[i] = 0x80000000u;
    asm volatile("barrier.cluster.arrive.aligned;" ::: "memory");
    asm volatile("barrier.cluster.wait.aligned;" ::: "memory");

    // ---- remote publish addresses (slot 0), staggered target order
    unsigned remS[NCTA];
    {
        unsigned laddr = sbase + 4u * (unsigned)(gw * 8 + (lane & 7));
#pragma unroll
        for (int t = 0; t < NCTA; t++)
            remS[t] = mapa_u32(laddr, (unsigned)((t + gw) & (NCTA - 1)));
    }

    // ---- log_b (base 2) for this lane's column class c = lane&7
    const int mycol = lane & 7;
    float lb_c;
    {
        float q[8];
#pragma unroll
        for (int j = 0; j < 8; j++) q[j] = phi[j] * L2E;
        float m = fmaxf(fmaxf(fmaxf(q[0], q[1]), fmaxf(q[2], q[3])),
                        fmaxf(fmaxf(q[4], q[5]), fmaxf(q[6], q[7])));
        float s = 0.f;
#pragma unroll
        for (int j = 0; j < 8; j++) s += ex2f(q[j] - m);
        lb_c = q[mycol] - m - lg2f(s);
    }

    // ---- per-row constants + K (base-2) + initial row softmax (g = 0)
    const float inv_sumn = 1.0f / g_sum_n;
    const float inv_sens = g_inv_sens;
    const float SC = 50.0f * L2E;

    float a[RPT], p[RPT][8];
    {
        const float4* n4 = (const float4*)(n_raw + base);
        const float4* s4 = (const float4*)(sens_raw + base);
        float4 nv = n4[0], sv = s4[0];
        float nn[RPT] = { nv.x, nv.y, nv.z, nv.w };
        float se[RPT] = { sv.x, sv.y, sv.z, sv.w };
        const float4* t4 = (const float4*)theta;
#pragma unroll
        for (int e = 0; e < RPT; e++) {
            float n  = nn[e] * 1e5f + 1e3f;
            a[e]     = n * inv_sumn;
            float cs = n * se[e] * inv_sens;
            int   r  = base + e;
            float4 ta = t4[r * 2], tb = t4[r * 2 + 1];
            float x[8];
            x[0] = (ta.x - cs * c_err[0]) * SC;
            x[1] = (ta.y - cs * c_err[1]) * SC;
            x[2] = (ta.z - cs * c_err[2]) * SC;
            x[3] = (ta.w - cs * c_err[3]) * SC;
            x[4] = (tb.x - cs * c_err[4]) * SC;
            x[5] = (tb.y - cs * c_err[5]) * SC;
            x[6] = (tb.z - cs * c_err[6]) * SC;
            x[7] = (tb.w - cs * c_err[7]) * SC;
            float m = fmaxf(fmaxf(fmaxf(x[0], x[1]), fmaxf(x[2], x[3])),
                            fmaxf(fmaxf(x[4], x[5]), fmaxf(x[6], x[7])));
            float S = 0.f;
#pragma unroll
            for (int j = 0; j < 8; j++) { p[e][j] = ex2f(x[j] - m); S += p[e][j]; }
            float ar = __fdividef(a[e], S);
#pragma unroll
            for (int j = 0; j < 8; j++) p[e][j] *= ar;   // P(f_1, g_0), rows sum to a
        }
    }

    float d[8], Tc = 1.f, dc = 1.f;

    for (int it = 0; it < NITER; ++it) {
        const int      slot = it & 1;
        const unsigned esgn = (unsigned)((it >> 1) & 1);

        // ---- column partials over this thread's 4 rows
        float c0[8];
#pragma unroll
        for (int j = 0; j < 8; j++)
            c0[j] = (p[0][j] + p[1][j]) + (p[2][j] + p[3][j]);

        // ---- butterfly transpose-reduce: lane holds warp col sum for col lane&7
        float z;
        {
            float s0 = __shfl_xor_sync(FULL, c0[0], 4);
            float s1 = __shfl_xor_sync(FULL, c0[1], 4);
            float s2 = __shfl_xor_sync(FULL, c0[2], 4);
            float s3 = __shfl_xor_sync(FULL, c0[3], 4);
            float s4 = __shfl_xor_sync(FULL, c0[4], 4);
            float s5 = __shfl_xor_sync(FULL, c0[5], 4);
            float s6 = __shfl_xor_sync(FULL, c0[6], 4);
            float s7 = __shfl_xor_sync(FULL, c0[7], 4);
            bool hi4 = (lane & 4) != 0;
            float u0 = hi4 ? (c0[4] + s4) : (c0[0] + s0);
            float u1 = hi4 ? (c0[5] + s5) : (c0[1] + s1);
            float u2 = hi4 ? (c0[6] + s6) : (c0[2] + s2);
            float u3 = hi4 ? (c0[7] + s7) : (c0[3] + s3);
            float r0 = __shfl_xor_sync(FULL, u0, 2);
            float r1 = __shfl_xor_sync(FULL, u1, 2);
            float r2 = __shfl_xor_sync(FULL, u2, 2);
            float r3 = __shfl_xor_sync(FULL, u3, 2);
            bool hi2 = (lane & 2) != 0;
            float w0 = hi2 ? (u2 + r2) : (u0 + r0);
            float w1 = hi2 ? (u3 + r3) : (u1 + r1);
            float q0 = __shfl_xor_sync(FULL, w0, 1);
            float q1 = __shfl_xor_sync(FULL, w1, 1);
            z = (lane & 1) ? (w1 + q1) : (w0 + q0);
            z += __shfl_xor_sync(FULL, z, 8);
            z += __shfl_xor_sync(FULL, z, 16);
        }

        // ---- publish to all 8 CTAs' poll buffers (lanes 0-7; value carries phase)
        if (lane < 8) {
            unsigned bits = (__float_as_uint(z) & 0x7fffffffu) | (esgn << 31);
            unsigned soff = (unsigned)slot * 2048u;
#pragma unroll
            for (int t = 0; t < NCTA; t++) st_cluster(remS[t] + soff, bits);
        }

        // ---- poll own SMEM: 16 values/lane at idx = lane + 32k (conflict-free,
        //      col class = lane&7 for all k; identical order in every warp)
        float v[16];
        unsigned got = 0;
        {
            unsigned pbase = sbase + (unsigned)slot * 2048u + 4u * (unsigned)lane;
            while (got != 0xffffu) {
#pragma unroll
                for (int k = 0; k < 16; k++) {
                    if (!((got >> k) & 1u)) {
                        unsigned b = ld_vol_shared(pbase + 128u * (unsigned)k);
                        if ((b >> 31) == esgn) {
                            v[k] = __uint_as_float(b & 0x7fffffffu);
                            got |= 1u << k;
                        }
                    }
                }
            }
        }
        float tsum = (((v[0] + v[1]) + (v[2] + v[3])) + ((v[4] + v[5]) + (v[6] + v[7])))
                   + (((v[8] + v[9]) + (v[10] + v[11])) + ((v[12] + v[13]) + (v[14] + v[15])));
        tsum += __shfl_xor_sync(FULL, tsum, 8);
        tsum += __shfl_xor_sync(FULL, tsum, 16);
        Tc = tsum;                                   // col sum, replicated per 8-group

        // ---- g update (base-2), per-column lane scalar; broadcast d_j within group
        float dgc = lb_c - lg2f(fmaxf(Tc, 1e-37f));
        dc = ex2f(dgc);
#pragma unroll
        for (int j = 0; j < 8; j++) d[j] = __shfl_sync(FULL, dc, j, 8);

        // ---- multiplicative row update (skip on last iter; final scaling below)
        if (it != NITER - 1) {
#pragma unroll
            for (int e = 0; e < RPT; e++) {
                float q[8];
#pragma unroll
                for (int j = 0; j < 8; j++) q[j] = p[e][j] * d[j];
                float S = ((q[0] + q[1]) + (q[2] + q[3])) + ((q[4] + q[5]) + (q[6] + q[7]));
                float ar = __fdividef(a[e], S);
#pragma unroll
                for (int j = 0; j < 8; j++) p[e][j] = q[j] * ar;
            }
        }
    }

    // ---- final: P = p * d / sum;  sum = sum_j T_j * d_j
    float tg = Tc * dc;
    tg += __shfl_xor_sync(FULL, tg, 1);
    tg += __shfl_xor_sync(FULL, tg, 2);
    tg += __shfl_xor_sync(FULL, tg, 4);
    float inv = 1.0f / (tg + 1e-40f);

    float4* out4 = (float4*)out;
#pragma unroll
    for (int e = 0; e < RPT; e++) {
        int r = base + e;
        float4 o0, o1;
        o0.x = p[e][0] * d[0] * inv;  o0.y = p[e][1] * d[1] * inv;
        o0.z = p[e][2] * d[2] * inv;  o0.w = p[e][3] * d[3] * inv;
        o1.x = p[e][4] * d[4] * inv;  o1.y = p[e][5] * d[5] * inv;
        o1.z = p[e][6] * d[6] * inv;  o1.w = p[e][7] * d[7] * inv;
        out4[r * 2]     = o0;
        out4[r * 2 + 1] = o1;
    }

    // no CTA may exit while peers might still touch its SMEM (poll completion
    // already implies all stores landed, but keep the architectural guarantee)
    asm volatile("barrier.cluster.arrive.aligned;" ::: "memory");
    asm volatile("barrier.cluster.wait.aligned;" ::: "memory");
}

// ---------------------------------------------------------------------------
extern "C" void kernel_launch(void* const* d_in, const int* in_sizes, int n_in,
                              void* d_out, int out_size) {
    const float* theta    = (const float*)d_in[0];
    const float* phi      = (const float*)d_in[1];
    const float* sens_raw = (const float*)d_in[2];
    const float* n_raw    = (const float*)d_in[3];
    float*       out      = (float*)d_out;

    da_pre_kernel<<<1, NT>>>(n_raw, sens_raw);
    da_main_kernel<<<NCTA, NT>>>(theta, phi, sens_raw, n_raw, out);
}